// round 10
// baseline (speedup 1.0000x reference)
#include <cuda_runtime.h>

#define T_LEN   4096
#define IN_SZ   128
#define R_SZ    2048
#define NCTA    128
#define ROWS_PER_CTA 16       // 2048 / 128
#define THREADS_SCAN 256
#define CHUNKS_PER_CTA 8      // one chunk per warp: {xA, xB, pad, tag}
#define NCHUNK (NCTA * CHUNKS_PER_CTA)   // 1024 == 4 * THREADS_SCAN
#define INV_SQRT_R 0.022097086912079608f // 1/sqrt(2048)

// Scratch: batched input projection U[t][r] = input[t] @ W_in^T + bias
__device__ float g_U[(size_t)T_LEN * R_SZ];
// Self-validating state chunks: {rowA, rowB, pad, tag_as_float}, double-
// buffered by step parity. Aligned STG.128 is single-copy atomic: tag==t
// (in .w!) implies the data floats in the same 16B word are step-t values.
__device__ float4 g_chunks[2][NCHUNK];

__device__ __forceinline__ float4 ld_chunk_volatile(const float4* p) {
    float4 v;
    asm volatile("ld.volatile.global.v4.f32 {%0,%1,%2,%3}, [%4];"
                 : "=f"(v.x), "=f"(v.y), "=f"(v.z), "=f"(v.w)
                 : "l"(p) : "memory");
    return v;
}
__device__ __forceinline__ void st_chunk_volatile(float4* p, float4 v) {
    asm volatile("st.volatile.global.v4.f32 [%0], {%1,%2,%3,%4};"
                 :: "l"(p), "f"(v.x), "f"(v.y), "f"(v.z), "f"(v.w)
                 : "memory");
}

// ---------------------------------------------------------------------------
// Reset all chunk tags (stale tags from a previous graph replay would
// otherwise satisfy this replay's polls with stale data).
// ---------------------------------------------------------------------------
__global__ void init_kernel() {
    int i = blockIdx.x * blockDim.x + threadIdx.x;   // 0 .. 2*NCHUNK-1
    ((float4*)g_chunks)[i] = make_float4(0.f, 0.f, 0.f, 0.f);
}

// ---------------------------------------------------------------------------
// Projection GEMM: U = input @ W_in^T + bias.  (4096 x 2048, K=128)
// ---------------------------------------------------------------------------
#define PJ_KT 32
__global__ __launch_bounds__(256) void proj_kernel(
    const float* __restrict__ inp,   // [T_LEN][IN_SZ]
    const float* __restrict__ Win,   // [R_SZ][IN_SZ]
    const float* __restrict__ bias)  // [R_SZ]
{
    __shared__ float sA[PJ_KT][64];  // [k][t]
    __shared__ float sB[PJ_KT][64];  // [k][r]

    const int tid = threadIdx.x;
    const int t0 = blockIdx.y * 64;
    const int r0 = blockIdx.x * 64;
    const int tx = tid & 15;
    const int ty = tid >> 4;

    float acc[4][4];
#pragma unroll
    for (int i = 0; i < 4; i++)
#pragma unroll
        for (int j = 0; j < 4; j++) acc[i][j] = 0.0f;

    for (int kc = 0; kc < IN_SZ; kc += PJ_KT) {
        __syncthreads();
#pragma unroll
        for (int it = 0; it < 2; it++) {
            int i   = tid + 256 * it;
            int row = i >> 3;
            int kq  = i & 7;
            float4 va = *(const float4*)(inp + (size_t)(t0 + row) * IN_SZ + kc + 4 * kq);
            sA[4 * kq + 0][row] = va.x;
            sA[4 * kq + 1][row] = va.y;
            sA[4 * kq + 2][row] = va.z;
            sA[4 * kq + 3][row] = va.w;
            float4 vb = *(const float4*)(Win + (size_t)(r0 + row) * IN_SZ + kc + 4 * kq);
            sB[4 * kq + 0][row] = vb.x;
            sB[4 * kq + 1][row] = vb.y;
            sB[4 * kq + 2][row] = vb.z;
            sB[4 * kq + 3][row] = vb.w;
        }
        __syncthreads();
#pragma unroll
        for (int k = 0; k < PJ_KT; k++) {
            float a[4], b[4];
#pragma unroll
            for (int i = 0; i < 4; i++) a[i] = sA[k][tx + 16 * i];
#pragma unroll
            for (int j = 0; j < 4; j++) b[j] = sB[k][ty + 16 * j];
#pragma unroll
            for (int i = 0; i < 4; i++)
#pragma unroll
                for (int j = 0; j < 4; j++) acc[i][j] += a[i] * b[j];
        }
    }

#pragma unroll
    for (int j = 0; j < 4; j++) {
        const int r = r0 + ty + 16 * j;
        const float bj = bias[r];
#pragma unroll
        for (int i = 0; i < 4; i++) {
            const int t = t0 + tx + 16 * i;
            g_U[(size_t)t * R_SZ + r] = acc[i][j] + bj;
        }
    }
}

// ---------------------------------------------------------------------------
// Persistent ESN scan. 128 CTAs, 16 rows each, weights register-resident.
// Per-warp IMMEDIATE tagged publish (tag in .w — the R6 hang was the tag
// written to .z but polled at .w), double-buffered state SMEM -> single
// __syncthreads per step, combined-retry batched poll (MLP=4).
// ---------------------------------------------------------------------------
__global__ __launch_bounds__(THREADS_SCAN, 1) void scan_kernel(
    const float* __restrict__ Wres,  // [R_SZ][R_SZ]
    float* __restrict__ out)         // [T_LEN][R_SZ]
{
    __shared__ float s_sm[2][R_SZ];          // double-buffered state, 16 KB

    const int tid  = threadIdx.x;
    const int warp = tid >> 5;
    const int lane = tid & 31;
    const int bid  = blockIdx.x;
    const int rowA = bid * ROWS_PER_CTA + 2 * warp;

    // Preload weights: thread (warp w, lane l) owns rows {rowA,rowA+1},
    // columns 4*l + 128*k (+0..3), k = 0..15.  128 scalar f32 regs.
    float4 wA[16], wB[16];
    {
        const float* pA = Wres + (size_t)rowA * R_SZ + 4 * lane;
        const float* pB = pA + R_SZ;
#pragma unroll
        for (int k = 0; k < 16; k++) {
            wA[k] = *(const float4*)(pA + 128 * k);
            wB[k] = *(const float4*)(pB + 128 * k);
        }
    }

    // lane 0 owns rowA's carry, lane 16 owns rowA+1's carry
    const bool is_owner = (lane == 0) || (lane == 16);
    const int  my_row   = rowA + (lane >> 4);
    float xp = 0.0f;                 // previous value of my_row

    const int c0 = 4 * tid;          // this thread's 4 chunks (64B span)

    for (int t = 0; t < T_LEN; t++) {
        float* sbuf = s_sm[t & 1];
        const float4* s4 = (const float4*)sbuf;

        // ---- hoisted independent load: input projection for this step ----
        float u = 0.f;
        if (is_owner) u = __ldg(g_U + (size_t)t * R_SZ + my_row);

        // ---- acquire state: batched poll, combined straggler retry ----
        if (t == 0) {
            for (int i = tid; i < R_SZ; i += THREADS_SCAN) sbuf[i] = 0.0f;
        } else {
            const float4* buf = g_chunks[t & 1];
            float4 v0 = ld_chunk_volatile(buf + c0 + 0);
            float4 v1 = ld_chunk_volatile(buf + c0 + 1);
            float4 v2 = ld_chunk_volatile(buf + c0 + 2);
            float4 v3 = ld_chunk_volatile(buf + c0 + 3);
            for (;;) {
                const bool b0 = (__float_as_int(v0.w) == t);
                const bool b1 = (__float_as_int(v1.w) == t);
                const bool b2 = (__float_as_int(v2.w) == t);
                const bool b3 = (__float_as_int(v3.w) == t);
                if (b0 && b1 && b2 && b3) break;
                // re-issue ALL stale loads back-to-back (keeps MLP high)
                if (!b0) v0 = ld_chunk_volatile(buf + c0 + 0);
                if (!b1) v1 = ld_chunk_volatile(buf + c0 + 1);
                if (!b2) v2 = ld_chunk_volatile(buf + c0 + 2);
                if (!b3) v3 = ld_chunk_volatile(buf + c0 + 3);
            }
            // chunk ch holds global rows {2ch, 2ch+1} -> rows 8*tid..8*tid+7
            float4* dst = (float4*)(sbuf + 8 * tid);
            dst[0] = make_float4(v0.x, v0.y, v1.x, v1.y);
            dst[1] = make_float4(v2.x, v2.y, v3.x, v3.y);
        }
        __syncthreads();   // the only barrier per step (s_sm double-buffered)

        // ---- register-resident matvec (R5-proven 2-accumulator form) ----
        float a0 = 0.f, a1 = 0.f;
#pragma unroll
        for (int k = 0; k < 16; k++) {
            const float4 sx = s4[lane + 32 * k];
            a0 += wA[k].x * sx.x; a0 += wA[k].y * sx.y;
            a0 += wA[k].z * sx.z; a0 += wA[k].w * sx.w;
            a1 += wB[k].x * sx.x; a1 += wB[k].y * sx.y;
            a1 += wB[k].z * sx.z; a1 += wB[k].w * sx.w;
        }

        // ---- split-half reduction: lane 0 -> row A, lane 16 -> row B ----
        a0 += __shfl_xor_sync(0xffffffffu, a0, 16);
        a1 += __shfl_xor_sync(0xffffffffu, a1, 16);
        float v = (lane < 16) ? a0 : a1;
#pragma unroll
        for (int off = 8; off > 0; off >>= 1)
            v += __shfl_xor_sync(0xffffffffu, v, off);

        // ---- owners update; lane 0 publishes this warp's chunk NOW ----
        float x = 0.0f;
        if (is_owner) {
            x = 0.1f * xp + 0.9f * erff(v + u) * INV_SQRT_R;
            xp = x;
        }
        const float xB = __shfl_sync(0xffffffffu, x, 16);
        if (lane == 0) {
            // tag goes in .w — polled at .w
            st_chunk_volatile(&g_chunks[(t + 1) & 1][bid * CHUNKS_PER_CTA + warp],
                              make_float4(x, xB, 0.0f, __int_as_float(t + 1)));
            *(float2*)(out + (size_t)t * R_SZ + rowA) = make_float2(x, xB);
        }
    }
}

// ---------------------------------------------------------------------------
extern "C" void kernel_launch(void* const* d_in, const int* in_sizes, int n_in,
                              void* d_out, int out_size)
{
    const float* input = (const float*)d_in[0];  // [4096][128]
    const float* Win   = (const float*)d_in[1];  // [2048][128]
    const float* Wres  = (const float*)d_in[2];  // [2048][2048]
    const float* bias  = (const float*)d_in[3];  // [2048]
    float* out = (float*)d_out;                  // [4096][2048]

    init_kernel<<<2 * NCHUNK / 256, 256>>>();

    dim3 pg(R_SZ / 64, T_LEN / 64);              // (32, 64)
    proj_kernel<<<pg, 256>>>(input, Win, bias);

    scan_kernel<<<NCTA, THREADS_SCAN>>>(Wres, out);
}

// round 12
// speedup vs baseline: 1.5558x; 1.5558x over previous
#include <cuda_runtime.h>

#define T_LEN   4096
#define IN_SZ   128
#define R_SZ    2048
#define NCTA    128
#define ROWS_PER_CTA 16       // 2048 / 128
#define THREADS_SCAN 256
#define CHUNKS_PER_CTA 6      // 16 rows -> 5 chunks x3 + 1 chunk x1
#define NCHUNK (NCTA * CHUNKS_PER_CTA)   // 768 == THREADS_SCAN * 3
#define INV_SQRT_R 0.022097086912079608f // 1/sqrt(2048)

// Scratch: batched input projection U[t][r] = input[t] @ W_in^T + bias
__device__ float g_U[(size_t)T_LEN * R_SZ];
// Self-validating state chunks: {d0,d1,d2, tag_as_float}, double-buffered by
// step parity. A 16B aligned STG.128 is single-copy atomic, so tag==t implies
// the 3 data floats in the same word are from step t. No fences, no flags.
__device__ float4 g_chunks[2][NCHUNK];

__device__ __forceinline__ float4 ld_chunk_volatile(const float4* p) {
    float4 v;
    asm volatile("ld.volatile.global.v4.f32 {%0,%1,%2,%3}, [%4];"
                 : "=f"(v.x), "=f"(v.y), "=f"(v.z), "=f"(v.w)
                 : "l"(p) : "memory");
    return v;
}
__device__ __forceinline__ void st_chunk_volatile(float4* p, float4 v) {
    asm volatile("st.volatile.global.v4.f32 [%0], {%1,%2,%3,%4};"
                 :: "l"(p), "f"(v.x), "f"(v.y), "f"(v.z), "f"(v.w)
                 : "memory");
}

// ---------------------------------------------------------------------------
// Reset all chunk tags (stale tags from a previous graph replay would
// otherwise satisfy this replay's polls with stale data).
// ---------------------------------------------------------------------------
__global__ void init_kernel() {
    int i = blockIdx.x * blockDim.x + threadIdx.x;   // 0 .. 2*NCHUNK-1
    ((float4*)g_chunks)[i] = make_float4(0.f, 0.f, 0.f, 0.f);
}

// ---------------------------------------------------------------------------
// Projection GEMM: U = input @ W_in^T + bias.  (4096 x 2048, K=128)
// ---------------------------------------------------------------------------
#define PJ_KT 32
__global__ __launch_bounds__(256) void proj_kernel(
    const float* __restrict__ inp,   // [T_LEN][IN_SZ]
    const float* __restrict__ Win,   // [R_SZ][IN_SZ]
    const float* __restrict__ bias)  // [R_SZ]
{
    __shared__ float sA[PJ_KT][64];  // [k][t]
    __shared__ float sB[PJ_KT][64];  // [k][r]

    const int tid = threadIdx.x;
    const int t0 = blockIdx.y * 64;
    const int r0 = blockIdx.x * 64;
    const int tx = tid & 15;
    const int ty = tid >> 4;

    float acc[4][4];
#pragma unroll
    for (int i = 0; i < 4; i++)
#pragma unroll
        for (int j = 0; j < 4; j++) acc[i][j] = 0.0f;

    for (int kc = 0; kc < IN_SZ; kc += PJ_KT) {
        __syncthreads();
#pragma unroll
        for (int it = 0; it < 2; it++) {
            int i   = tid + 256 * it;
            int row = i >> 3;
            int kq  = i & 7;
            float4 va = *(const float4*)(inp + (size_t)(t0 + row) * IN_SZ + kc + 4 * kq);
            sA[4 * kq + 0][row] = va.x;
            sA[4 * kq + 1][row] = va.y;
            sA[4 * kq + 2][row] = va.z;
            sA[4 * kq + 3][row] = va.w;
            float4 vb = *(const float4*)(Win + (size_t)(r0 + row) * IN_SZ + kc + 4 * kq);
            sB[4 * kq + 0][row] = vb.x;
            sB[4 * kq + 1][row] = vb.y;
            sB[4 * kq + 2][row] = vb.z;
            sB[4 * kq + 3][row] = vb.w;
        }
        __syncthreads();
#pragma unroll
        for (int k = 0; k < PJ_KT; k++) {
            float a[4], b[4];
#pragma unroll
            for (int i = 0; i < 4; i++) a[i] = sA[k][tx + 16 * i];
#pragma unroll
            for (int j = 0; j < 4; j++) b[j] = sB[k][ty + 16 * j];
#pragma unroll
            for (int i = 0; i < 4; i++)
#pragma unroll
                for (int j = 0; j < 4; j++) acc[i][j] += a[i] * b[j];
        }
    }

#pragma unroll
    for (int j = 0; j < 4; j++) {
        const int r = r0 + ty + 16 * j;
        const float bj = bias[r];
#pragma unroll
        for (int i = 0; i < 4; i++) {
            const int t = t0 + tx + 16 * i;
            g_U[(size_t)t * R_SZ + r] = acc[i][j] + bj;
        }
    }
}

// ---------------------------------------------------------------------------
// Persistent ESN scan — R5 skeleton verbatim (6846us proven):
// serial chunk polls -> s_sm -> sync -> matvec -> reduce -> r_sm -> sync ->
// warp-7 publish. Single delta vs R5: __nanosleep backoff on poll misses to
// cut spin-induced L2 congestion (R7/R10 showed MORE poll traffic = slower).
// ---------------------------------------------------------------------------
__global__ __launch_bounds__(THREADS_SCAN, 1) void scan_kernel(
    const float* __restrict__ Wres,  // [R_SZ][R_SZ]
    float* __restrict__ out)         // [T_LEN][R_SZ]
{
    __shared__ float  s_sm[R_SZ];            // full state, 8 KB
    __shared__ float  r_sm[ROWS_PER_CTA];    // this CTA's 16 new values

    const float4* s_sm4 = (const float4*)s_sm;

    const int tid  = threadIdx.x;
    const int warp = tid >> 5;
    const int lane = tid & 31;
    const int bid  = blockIdx.x;
    const int rowA = bid * ROWS_PER_CTA + 2 * warp;

    // Preload weights: thread (warp w, lane l) owns rows {rowA,rowA+1},
    // columns 4*l + 128*k (+0..3), k = 0..15.  128 scalar f32 regs.
    float4 wA[16], wB[16];
    {
        const float* pA = Wres + (size_t)rowA * R_SZ + 4 * lane;
        const float* pB = pA + R_SZ;
#pragma unroll
        for (int k = 0; k < 16; k++) {
            wA[k] = *(const float4*)(pA + 128 * k);
            wB[k] = *(const float4*)(pB + 128 * k);
        }
    }

    // lane 0 owns rowA's carry, lane 16 owns rowA+1's carry
    const bool is_owner = (lane == 0) || (lane == 16);
    const int  my_row   = rowA + (lane >> 4);
    float xp = 0.0f;                 // previous value of my_row

    // This thread's 3 chunks (NCHUNK == 3 * THREADS_SCAN).
    const int ch0 = tid * 3;

    for (int t = 0; t < T_LEN; t++) {
        // ---- hoisted independent load: input projection for this step ----
        float u = 0.f;
        if (is_owner) u = __ldg(g_U + (size_t)t * R_SZ + my_row);

        // ---- acquire state for step t: serial polls with sleep backoff ----
        if (t == 0) {
            for (int i = tid; i < R_SZ; i += THREADS_SCAN) s_sm[i] = 0.0f;
        } else {
            const float4* buf = g_chunks[t & 1];
#pragma unroll
            for (int i = 0; i < 3; i++) {
                const int ch  = ch0 + i;
                const int sub = ch % CHUNKS_PER_CTA;              // 0..5
                const int row = (ch / CHUNKS_PER_CTA) * ROWS_PER_CTA + 3 * sub;
                float4 v = ld_chunk_volatile(buf + ch);
                while (__float_as_int(v.w) != t) {
                    __nanosleep(50);          // throttle spin -> less L2 traffic
                    v = ld_chunk_volatile(buf + ch);
                }
                s_sm[row] = v.x;
                if (sub < 5) { s_sm[row + 1] = v.y; s_sm[row + 2] = v.z; }
            }
        }
        __syncthreads();

        // ---- register-resident matvec (R5-proven 2-accumulator form) ----
        float a0 = 0.f, a1 = 0.f;
#pragma unroll
        for (int k = 0; k < 16; k++) {
            const float4 s4 = s_sm4[lane + 32 * k];
            a0 += wA[k].x * s4.x; a0 += wA[k].y * s4.y;
            a0 += wA[k].z * s4.z; a0 += wA[k].w * s4.w;
            a1 += wB[k].x * s4.x; a1 += wB[k].y * s4.y;
            a1 += wB[k].z * s4.z; a1 += wB[k].w * s4.w;
        }

        // ---- split-half reduction: lane 0 -> row A, lane 16 -> row B ----
        a0 += __shfl_xor_sync(0xffffffffu, a0, 16);
        a1 += __shfl_xor_sync(0xffffffffu, a1, 16);
        float v = (lane < 16) ? a0 : a1;
#pragma unroll
        for (int off = 8; off > 0; off >>= 1)
            v += __shfl_xor_sync(0xffffffffu, v, off);

        if (is_owner) {
            const float x = 0.1f * xp + 0.9f * erff(v + u) * INV_SQRT_R;
            xp = x;
            r_sm[2 * warp + (lane >> 4)] = x;
        }
        __syncthreads();

        // ---- publish: tagged chunks (warp 7 lanes 0-5, one STG.128 each,
        //      atomic data+tag => no fence), plain output store (warp 6). ----
        if (warp == 7 && lane < CHUNKS_PER_CTA) {
            float4 c;
            const int r3 = 3 * lane;
            c.x = r_sm[r3];
            c.y = (lane < 5) ? r_sm[r3 + 1] : 0.0f;
            c.z = (lane < 5) ? r_sm[r3 + 2] : 0.0f;
            c.w = __int_as_float(t + 1);
            st_chunk_volatile(&g_chunks[(t + 1) & 1][bid * CHUNKS_PER_CTA + lane], c);
        }
        if (warp == 6 && lane < 4) {
            float4* dst = (float4*)(out + (size_t)t * R_SZ + bid * ROWS_PER_CTA);
            dst[lane] = ((const float4*)r_sm)[lane];
        }
    }
}

// ---------------------------------------------------------------------------
extern "C" void kernel_launch(void* const* d_in, const int* in_sizes, int n_in,
                              void* d_out, int out_size)
{
    const float* input = (const float*)d_in[0];  // [4096][128]
    const float* Win   = (const float*)d_in[1];  // [2048][128]
    const float* Wres  = (const float*)d_in[2];  // [2048][2048]
    const float* bias  = (const float*)d_in[3];  // [2048]
    float* out = (float*)d_out;                  // [4096][2048]

    init_kernel<<<2 * NCHUNK / 256, 256>>>();

    dim3 pg(R_SZ / 64, T_LEN / 64);              // (32, 64)
    proj_kernel<<<pg, 256>>>(input, Win, bias);

    scan_kernel<<<NCTA, THREADS_SCAN>>>(Wres, out);
}

// round 13
// speedup vs baseline: 1.6441x; 1.0568x over previous
#include <cuda_runtime.h>

#define T_LEN   4096
#define IN_SZ   128
#define R_SZ    2048
#define NCTA    128
#define ROWS_PER_CTA 16       // 2048 / 128
#define THREADS_SCAN 256
#define CHUNKS_PER_CTA 6      // 16 rows -> 5 chunks x3 + 1 chunk x1
#define NCHUNK (NCTA * CHUNKS_PER_CTA)   // 768 == THREADS_SCAN * 3
#define INV_SQRT_R 0.022097086912079608f // 1/sqrt(2048)

// Scratch: batched input projection U[t][r] = input[t] @ W_in^T + bias
__device__ float g_U[(size_t)T_LEN * R_SZ];
// Self-validating state chunks: {d0,d1,d2, tag_as_float}, double-buffered by
// step parity. A 16B aligned STG.128 is single-copy atomic, so tag==t implies
// the 3 data floats in the same word are from step t. No fences, no flags.
__device__ float4 g_chunks[2][NCHUNK];

__device__ __forceinline__ float4 ld_chunk_volatile(const float4* p) {
    float4 v;
    asm volatile("ld.volatile.global.v4.f32 {%0,%1,%2,%3}, [%4];"
                 : "=f"(v.x), "=f"(v.y), "=f"(v.z), "=f"(v.w)
                 : "l"(p) : "memory");
    return v;
}
__device__ __forceinline__ void st_chunk_volatile(float4* p, float4 v) {
    asm volatile("st.volatile.global.v4.f32 [%0], {%1,%2,%3,%4};"
                 :: "l"(p), "f"(v.x), "f"(v.y), "f"(v.z), "f"(v.w)
                 : "memory");
}

// ---------------------------------------------------------------------------
// Reset all chunk tags (stale tags from a previous graph replay would
// otherwise satisfy this replay's polls with stale data).
// ---------------------------------------------------------------------------
__global__ void init_kernel() {
    int i = blockIdx.x * blockDim.x + threadIdx.x;   // 0 .. 2*NCHUNK-1
    ((float4*)g_chunks)[i] = make_float4(0.f, 0.f, 0.f, 0.f);
}

// ---------------------------------------------------------------------------
// Projection GEMM: U = input @ W_in^T + bias.  (4096 x 2048, K=128)
// ---------------------------------------------------------------------------
#define PJ_KT 32
__global__ __launch_bounds__(256) void proj_kernel(
    const float* __restrict__ inp,   // [T_LEN][IN_SZ]
    const float* __restrict__ Win,   // [R_SZ][IN_SZ]
    const float* __restrict__ bias)  // [R_SZ]
{
    __shared__ float sA[PJ_KT][64];  // [k][t]
    __shared__ float sB[PJ_KT][64];  // [k][r]

    const int tid = threadIdx.x;
    const int t0 = blockIdx.y * 64;
    const int r0 = blockIdx.x * 64;
    const int tx = tid & 15;
    const int ty = tid >> 4;

    float acc[4][4];
#pragma unroll
    for (int i = 0; i < 4; i++)
#pragma unroll
        for (int j = 0; j < 4; j++) acc[i][j] = 0.0f;

    for (int kc = 0; kc < IN_SZ; kc += PJ_KT) {
        __syncthreads();
#pragma unroll
        for (int it = 0; it < 2; it++) {
            int i   = tid + 256 * it;
            int row = i >> 3;
            int kq  = i & 7;
            float4 va = *(const float4*)(inp + (size_t)(t0 + row) * IN_SZ + kc + 4 * kq);
            sA[4 * kq + 0][row] = va.x;
            sA[4 * kq + 1][row] = va.y;
            sA[4 * kq + 2][row] = va.z;
            sA[4 * kq + 3][row] = va.w;
            float4 vb = *(const float4*)(Win + (size_t)(r0 + row) * IN_SZ + kc + 4 * kq);
            sB[4 * kq + 0][row] = vb.x;
            sB[4 * kq + 1][row] = vb.y;
            sB[4 * kq + 2][row] = vb.z;
            sB[4 * kq + 3][row] = vb.w;
        }
        __syncthreads();
#pragma unroll
        for (int k = 0; k < PJ_KT; k++) {
            float a[4], b[4];
#pragma unroll
            for (int i = 0; i < 4; i++) a[i] = sA[k][tx + 16 * i];
#pragma unroll
            for (int j = 0; j < 4; j++) b[j] = sB[k][ty + 16 * j];
#pragma unroll
            for (int i = 0; i < 4; i++)
#pragma unroll
                for (int j = 0; j < 4; j++) acc[i][j] += a[i] * b[j];
        }
    }

#pragma unroll
    for (int j = 0; j < 4; j++) {
        const int r = r0 + ty + 16 * j;
        const float bj = bias[r];
#pragma unroll
        for (int i = 0; i < 4; i++) {
            const int t = t0 + tx + 16 * i;
            g_U[(size_t)t * R_SZ + r] = acc[i][j] + bj;
        }
    }
}

// ---------------------------------------------------------------------------
// Persistent ESN scan — R5 skeleton (6846us proven), SINGLE delta:
// the 3 chunk loads are issued up-front (MLP=3) before the retry loops.
// Matvec stays the R5 2-accumulator form (this isolates the poll variable
// that was confounded with the matvec change in R7).
// ---------------------------------------------------------------------------
__global__ __launch_bounds__(THREADS_SCAN, 1) void scan_kernel(
    const float* __restrict__ Wres,  // [R_SZ][R_SZ]
    float* __restrict__ out)         // [T_LEN][R_SZ]
{
    __shared__ float  s_sm[R_SZ];            // full state, 8 KB
    __shared__ float  r_sm[ROWS_PER_CTA];    // this CTA's 16 new values

    const float4* s_sm4 = (const float4*)s_sm;

    const int tid  = threadIdx.x;
    const int warp = tid >> 5;
    const int lane = tid & 31;
    const int bid  = blockIdx.x;
    const int rowA = bid * ROWS_PER_CTA + 2 * warp;

    // Preload weights: thread (warp w, lane l) owns rows {rowA,rowA+1},
    // columns 4*l + 128*k (+0..3), k = 0..15.  128 scalar f32 regs.
    float4 wA[16], wB[16];
    {
        const float* pA = Wres + (size_t)rowA * R_SZ + 4 * lane;
        const float* pB = pA + R_SZ;
#pragma unroll
        for (int k = 0; k < 16; k++) {
            wA[k] = *(const float4*)(pA + 128 * k);
            wB[k] = *(const float4*)(pB + 128 * k);
        }
    }

    // lane 0 owns rowA's carry, lane 16 owns rowA+1's carry
    const bool is_owner = (lane == 0) || (lane == 16);
    const int  my_row   = rowA + (lane >> 4);
    float xp = 0.0f;                 // previous value of my_row

    // This thread's 3 chunks (NCHUNK == 3 * THREADS_SCAN). The triple
    // {3*tid, 3*tid+1, 3*tid+2} always lies within ONE producer CTA's group
    // (3 divides 6), so all three tags are published by one warp-instruction.
    const int ch0  = tid * 3;
    const int sub0 = ch0 % CHUNKS_PER_CTA;
    const int rb0  = (ch0 / CHUNKS_PER_CTA) * ROWS_PER_CTA + 3 * sub0;
    const int sub1 = (ch0 + 1) % CHUNKS_PER_CTA;
    const int rb1  = ((ch0 + 1) / CHUNKS_PER_CTA) * ROWS_PER_CTA + 3 * sub1;
    const int sub2 = (ch0 + 2) % CHUNKS_PER_CTA;
    const int rb2  = ((ch0 + 2) / CHUNKS_PER_CTA) * ROWS_PER_CTA + 3 * sub2;

    for (int t = 0; t < T_LEN; t++) {
        // ---- hoisted independent load: input projection for this step ----
        float u = 0.f;
        if (is_owner) u = __ldg(g_U + (size_t)t * R_SZ + my_row);

        // ---- acquire state: up-front batched loads, then ordered retries ----
        if (t == 0) {
            for (int i = tid; i < R_SZ; i += THREADS_SCAN) s_sm[i] = 0.0f;
        } else {
            const float4* buf = g_chunks[t & 1];
            float4 v0 = ld_chunk_volatile(buf + ch0 + 0);
            float4 v1 = ld_chunk_volatile(buf + ch0 + 1);
            float4 v2 = ld_chunk_volatile(buf + ch0 + 2);
            while (__float_as_int(v0.w) != t) v0 = ld_chunk_volatile(buf + ch0 + 0);
            while (__float_as_int(v1.w) != t) v1 = ld_chunk_volatile(buf + ch0 + 1);
            while (__float_as_int(v2.w) != t) v2 = ld_chunk_volatile(buf + ch0 + 2);

            s_sm[rb0] = v0.x;
            if (sub0 < 5) { s_sm[rb0 + 1] = v0.y; s_sm[rb0 + 2] = v0.z; }
            s_sm[rb1] = v1.x;
            if (sub1 < 5) { s_sm[rb1 + 1] = v1.y; s_sm[rb1 + 2] = v1.z; }
            s_sm[rb2] = v2.x;
            if (sub2 < 5) { s_sm[rb2 + 1] = v2.y; s_sm[rb2 + 2] = v2.z; }
        }
        __syncthreads();

        // ---- register-resident matvec (R5-proven 2-accumulator form) ----
        float a0 = 0.f, a1 = 0.f;
#pragma unroll
        for (int k = 0; k < 16; k++) {
            const float4 s4 = s_sm4[lane + 32 * k];
            a0 += wA[k].x * s4.x; a0 += wA[k].y * s4.y;
            a0 += wA[k].z * s4.z; a0 += wA[k].w * s4.w;
            a1 += wB[k].x * s4.x; a1 += wB[k].y * s4.y;
            a1 += wB[k].z * s4.z; a1 += wB[k].w * s4.w;
        }

        // ---- split-half reduction: lane 0 -> row A, lane 16 -> row B ----
        a0 += __shfl_xor_sync(0xffffffffu, a0, 16);
        a1 += __shfl_xor_sync(0xffffffffu, a1, 16);
        float v = (lane < 16) ? a0 : a1;
#pragma unroll
        for (int off = 8; off > 0; off >>= 1)
            v += __shfl_xor_sync(0xffffffffu, v, off);

        if (is_owner) {
            const float x = 0.1f * xp + 0.9f * erff(v + u) * INV_SQRT_R;
            xp = x;
            r_sm[2 * warp + (lane >> 4)] = x;
        }
        __syncthreads();

        // ---- publish: tagged chunks (warp 7 lanes 0-5, one STG.128 each,
        //      atomic data+tag => no fence), plain output store (warp 6). ----
        if (warp == 7 && lane < CHUNKS_PER_CTA) {
            float4 c;
            const int r3 = 3 * lane;
            c.x = r_sm[r3];
            c.y = (lane < 5) ? r_sm[r3 + 1] : 0.0f;
            c.z = (lane < 5) ? r_sm[r3 + 2] : 0.0f;
            c.w = __int_as_float(t + 1);
            st_chunk_volatile(&g_chunks[(t + 1) & 1][bid * CHUNKS_PER_CTA + lane], c);
        }
        if (warp == 6 && lane < 4) {
            float4* dst = (float4*)(out + (size_t)t * R_SZ + bid * ROWS_PER_CTA);
            dst[lane] = ((const float4*)r_sm)[lane];
        }
    }
}

// ---------------------------------------------------------------------------
extern "C" void kernel_launch(void* const* d_in, const int* in_sizes, int n_in,
                              void* d_out, int out_size)
{
    const float* input = (const float*)d_in[0];  // [4096][128]
    const float* Win   = (const float*)d_in[1];  // [2048][128]
    const float* Wres  = (const float*)d_in[2];  // [2048][2048]
    const float* bias  = (const float*)d_in[3];  // [2048]
    float* out = (float*)d_out;                  // [4096][2048]

    init_kernel<<<2 * NCHUNK / 256, 256>>>();

    dim3 pg(R_SZ / 64, T_LEN / 64);              // (32, 64)
    proj_kernel<<<pg, 256>>>(input, Win, bias);

    scan_kernel<<<NCTA, THREADS_SCAN>>>(Wres, out);
}

// round 14
// speedup vs baseline: 1.8512x; 1.1260x over previous
#include <cuda_runtime.h>

#define T_LEN   4096
#define IN_SZ   128
#define R_SZ    2048
#define NCTA    128
#define ROWS_PER_CTA 16       // 2048 / 128
#define THREADS_SCAN 256
#define CHUNKS_PER_CTA 6      // 16 rows -> 5 chunks x3 + 1 chunk x1
#define NCHUNK (NCTA * CHUNKS_PER_CTA)   // 768 == THREADS_SCAN * 3
#define INV_SQRT_R 0.022097086912079608f // 1/sqrt(2048)

// Scratch: batched input projection U[t][r] = input[t] @ W_in^T + bias
__device__ float g_U[(size_t)T_LEN * R_SZ];
// Self-validating state chunks: {d0,d1,d2, tag_as_float}, double-buffered by
// step parity. A 16B aligned STG.128 is single-copy atomic, so tag==t implies
// the 3 data floats in the same word are from step t. No fences, no flags.
__device__ float4 g_chunks[2][NCHUNK];

__device__ __forceinline__ float4 ld_chunk_volatile(const float4* p) {
    float4 v;
    asm volatile("ld.volatile.global.v4.f32 {%0,%1,%2,%3}, [%4];"
                 : "=f"(v.x), "=f"(v.y), "=f"(v.z), "=f"(v.w)
                 : "l"(p) : "memory");
    return v;
}
__device__ __forceinline__ void st_chunk_volatile(float4* p, float4 v) {
    asm volatile("st.volatile.global.v4.f32 [%0], {%1,%2,%3,%4};"
                 :: "l"(p), "f"(v.x), "f"(v.y), "f"(v.z), "f"(v.w)
                 : "memory");
}

// ---------------------------------------------------------------------------
// Reset all chunk tags (stale tags from a previous graph replay would
// otherwise satisfy this replay's polls with stale data).
// ---------------------------------------------------------------------------
__global__ void init_kernel() {
    int i = blockIdx.x * blockDim.x + threadIdx.x;   // 0 .. 2*NCHUNK-1
    ((float4*)g_chunks)[i] = make_float4(0.f, 0.f, 0.f, 0.f);
}

// ---------------------------------------------------------------------------
// Projection GEMM: U = input @ W_in^T + bias.  (4096 x 2048, K=128)
// ---------------------------------------------------------------------------
#define PJ_KT 32
__global__ __launch_bounds__(256) void proj_kernel(
    const float* __restrict__ inp,   // [T_LEN][IN_SZ]
    const float* __restrict__ Win,   // [R_SZ][IN_SZ]
    const float* __restrict__ bias)  // [R_SZ]
{
    __shared__ float sA[PJ_KT][64];  // [k][t]
    __shared__ float sB[PJ_KT][64];  // [k][r]

    const int tid = threadIdx.x;
    const int t0 = blockIdx.y * 64;
    const int r0 = blockIdx.x * 64;
    const int tx = tid & 15;
    const int ty = tid >> 4;

    float acc[4][4];
#pragma unroll
    for (int i = 0; i < 4; i++)
#pragma unroll
        for (int j = 0; j < 4; j++) acc[i][j] = 0.0f;

    for (int kc = 0; kc < IN_SZ; kc += PJ_KT) {
        __syncthreads();
#pragma unroll
        for (int it = 0; it < 2; it++) {
            int i   = tid + 256 * it;
            int row = i >> 3;
            int kq  = i & 7;
            float4 va = *(const float4*)(inp + (size_t)(t0 + row) * IN_SZ + kc + 4 * kq);
            sA[4 * kq + 0][row] = va.x;
            sA[4 * kq + 1][row] = va.y;
            sA[4 * kq + 2][row] = va.z;
            sA[4 * kq + 3][row] = va.w;
            float4 vb = *(const float4*)(Win + (size_t)(r0 + row) * IN_SZ + kc + 4 * kq);
            sB[4 * kq + 0][row] = vb.x;
            sB[4 * kq + 1][row] = vb.y;
            sB[4 * kq + 2][row] = vb.z;
            sB[4 * kq + 3][row] = vb.w;
        }
        __syncthreads();
#pragma unroll
        for (int k = 0; k < PJ_KT; k++) {
            float a[4], b[4];
#pragma unroll
            for (int i = 0; i < 4; i++) a[i] = sA[k][tx + 16 * i];
#pragma unroll
            for (int j = 0; j < 4; j++) b[j] = sB[k][ty + 16 * j];
#pragma unroll
            for (int i = 0; i < 4; i++)
#pragma unroll
                for (int j = 0; j < 4; j++) acc[i][j] += a[i] * b[j];
        }
    }

#pragma unroll
    for (int j = 0; j < 4; j++) {
        const int r = r0 + ty + 16 * j;
        const float bj = bias[r];
#pragma unroll
        for (int i = 0; i < 4; i++) {
            const int t = t0 + tx + 16 * i;
            g_U[(size_t)t * R_SZ + r] = acc[i][j] + bj;
        }
    }
}

// ---------------------------------------------------------------------------
// Persistent ESN scan — R5 skeleton (6846us proven), SINGLE delta:
// tail-batch poll. Chunk0 spins serially exactly as R5 (minimum traffic);
// once its tag hits, chunks 1,2 — published by the SAME producer warp
// instruction, hence guaranteed ready — are issued back-to-back (MLP=2,
// first-try hits). Same load count as R5, one L2 RT instead of two.
// ---------------------------------------------------------------------------
__global__ __launch_bounds__(THREADS_SCAN, 1) void scan_kernel(
    const float* __restrict__ Wres,  // [R_SZ][R_SZ]
    float* __restrict__ out)         // [T_LEN][R_SZ]
{
    __shared__ float  s_sm[R_SZ];            // full state, 8 KB
    __shared__ float  r_sm[ROWS_PER_CTA];    // this CTA's 16 new values

    const float4* s_sm4 = (const float4*)s_sm;

    const int tid  = threadIdx.x;
    const int warp = tid >> 5;
    const int lane = tid & 31;
    const int bid  = blockIdx.x;
    const int rowA = bid * ROWS_PER_CTA + 2 * warp;

    // Preload weights: thread (warp w, lane l) owns rows {rowA,rowA+1},
    // columns 4*l + 128*k (+0..3), k = 0..15.  128 scalar f32 regs.
    float4 wA[16], wB[16];
    {
        const float* pA = Wres + (size_t)rowA * R_SZ + 4 * lane;
        const float* pB = pA + R_SZ;
#pragma unroll
        for (int k = 0; k < 16; k++) {
            wA[k] = *(const float4*)(pA + 128 * k);
            wB[k] = *(const float4*)(pB + 128 * k);
        }
    }

    // lane 0 owns rowA's carry, lane 16 owns rowA+1's carry
    const bool is_owner = (lane == 0) || (lane == 16);
    const int  my_row   = rowA + (lane >> 4);
    float xp = 0.0f;                 // previous value of my_row

    // This thread's 3 chunks (NCHUNK == 3 * THREADS_SCAN). The triple
    // {3*tid, 3*tid+1, 3*tid+2} always lies within ONE producer CTA's group
    // (3 divides 6), so all three tags are published by one warp-instruction:
    // chunk0's tag hit implies chunks 1,2 are ready.
    const int ch0  = tid * 3;
    const int sub0 = ch0 % CHUNKS_PER_CTA;
    const int rb0  = (ch0 / CHUNKS_PER_CTA) * ROWS_PER_CTA + 3 * sub0;
    const int sub1 = (ch0 + 1) % CHUNKS_PER_CTA;
    const int rb1  = ((ch0 + 1) / CHUNKS_PER_CTA) * ROWS_PER_CTA + 3 * sub1;
    const int sub2 = (ch0 + 2) % CHUNKS_PER_CTA;
    const int rb2  = ((ch0 + 2) / CHUNKS_PER_CTA) * ROWS_PER_CTA + 3 * sub2;

    for (int t = 0; t < T_LEN; t++) {
        // ---- hoisted independent load: input projection for this step ----
        float u = 0.f;
        if (is_owner) u = __ldg(g_U + (size_t)t * R_SZ + my_row);

        // ---- acquire state: serial spin on chunk0, then tail-batch 1,2 ----
        if (t == 0) {
            for (int i = tid; i < R_SZ; i += THREADS_SCAN) s_sm[i] = 0.0f;
        } else {
            const float4* buf = g_chunks[t & 1];
            // chunk0: exact R5 spin (minimum in-flight traffic while waiting)
            float4 v0 = ld_chunk_volatile(buf + ch0 + 0);
            while (__float_as_int(v0.w) != t) v0 = ld_chunk_volatile(buf + ch0 + 0);
            // chunks 1,2: guaranteed ready now -> issue back-to-back (MLP=2)
            float4 v1 = ld_chunk_volatile(buf + ch0 + 1);
            float4 v2 = ld_chunk_volatile(buf + ch0 + 2);
            while (__float_as_int(v1.w) != t) v1 = ld_chunk_volatile(buf + ch0 + 1);
            while (__float_as_int(v2.w) != t) v2 = ld_chunk_volatile(buf + ch0 + 2);

            s_sm[rb0] = v0.x;
            if (sub0 < 5) { s_sm[rb0 + 1] = v0.y; s_sm[rb0 + 2] = v0.z; }
            s_sm[rb1] = v1.x;
            if (sub1 < 5) { s_sm[rb1 + 1] = v1.y; s_sm[rb1 + 2] = v1.z; }
            s_sm[rb2] = v2.x;
            if (sub2 < 5) { s_sm[rb2 + 1] = v2.y; s_sm[rb2 + 2] = v2.z; }
        }
        __syncthreads();

        // ---- register-resident matvec (R5-proven 2-accumulator form) ----
        float a0 = 0.f, a1 = 0.f;
#pragma unroll
        for (int k = 0; k < 16; k++) {
            const float4 s4 = s_sm4[lane + 32 * k];
            a0 += wA[k].x * s4.x; a0 += wA[k].y * s4.y;
            a0 += wA[k].z * s4.z; a0 += wA[k].w * s4.w;
            a1 += wB[k].x * s4.x; a1 += wB[k].y * s4.y;
            a1 += wB[k].z * s4.z; a1 += wB[k].w * s4.w;
        }

        // ---- split-half reduction: lane 0 -> row A, lane 16 -> row B ----
        a0 += __shfl_xor_sync(0xffffffffu, a0, 16);
        a1 += __shfl_xor_sync(0xffffffffu, a1, 16);
        float v = (lane < 16) ? a0 : a1;
#pragma unroll
        for (int off = 8; off > 0; off >>= 1)
            v += __shfl_xor_sync(0xffffffffu, v, off);

        if (is_owner) {
            const float x = 0.1f * xp + 0.9f * erff(v + u) * INV_SQRT_R;
            xp = x;
            r_sm[2 * warp + (lane >> 4)] = x;
        }
        __syncthreads();

        // ---- publish: tagged chunks (warp 7 lanes 0-5, one STG.128 each,
        //      atomic data+tag => no fence), plain output store (warp 6). ----
        if (warp == 7 && lane < CHUNKS_PER_CTA) {
            float4 c;
            const int r3 = 3 * lane;
            c.x = r_sm[r3];
            c.y = (lane < 5) ? r_sm[r3 + 1] : 0.0f;
            c.z = (lane < 5) ? r_sm[r3 + 2] : 0.0f;
            c.w = __int_as_float(t + 1);
            st_chunk_volatile(&g_chunks[(t + 1) & 1][bid * CHUNKS_PER_CTA + lane], c);
        }
        if (warp == 6 && lane < 4) {
            float4* dst = (float4*)(out + (size_t)t * R_SZ + bid * ROWS_PER_CTA);
            dst[lane] = ((const float4*)r_sm)[lane];
        }
    }
}

// ---------------------------------------------------------------------------
extern "C" void kernel_launch(void* const* d_in, const int* in_sizes, int n_in,
                              void* d_out, int out_size)
{
    const float* input = (const float*)d_in[0];  // [4096][128]
    const float* Win   = (const float*)d_in[1];  // [2048][128]
    const float* Wres  = (const float*)d_in[2];  // [2048][2048]
    const float* bias  = (const float*)d_in[3];  // [2048]
    float* out = (float*)d_out;                  // [4096][2048]

    init_kernel<<<2 * NCHUNK / 256, 256>>>();

    dim3 pg(R_SZ / 64, T_LEN / 64);              // (32, 64)
    proj_kernel<<<pg, 256>>>(input, Win, bias);

    scan_kernel<<<NCTA, THREADS_SCAN>>>(Wres, out);
}